// round 10
// baseline (speedup 1.0000x reference)
#include <cuda_runtime.h>
#include <cuda_bf16.h>
#include <stdint.h>

namespace {

constexpr int Bb = 4, Ss = 2048, Hh = 16, Dd = 64;
constexpr int BM = 128, BN = 64;
constexpr int KP = 36;            // u32 per sK row (f16x2 words): frag bank = 4g+c, conflict-free
constexpr int VP = 72;            // u32 per sV row-pair: frag bank = 8c+g, conflict-free
constexpr float SCALE = 0.125f;   // 1/sqrt(64)
constexpr float LOG2E = 1.4426950408889634f;
constexpr float NEGINF = -1e30f;

__device__ __forceinline__ uint32_t packf16x2(float lo, float hi) {
    uint32_t r;
    asm("cvt.rn.f16x2.f32 %0, %1, %2;" : "=r"(r) : "f"(hi), "f"(lo));
    return r;
}
__device__ __forceinline__ uint32_t ex2h2(uint32_t x) {
    uint32_t r;
    asm("ex2.approx.f16x2 %0, %1;" : "=r"(r) : "r"(x));
    return r;
}

__device__ __forceinline__ void mma_f16(float c[4], const uint32_t a[4], const uint32_t b[2]) {
    asm volatile(
        "mma.sync.aligned.m16n8k16.row.col.f32.f16.f16.f32 "
        "{%0,%1,%2,%3}, {%4,%5,%6,%7}, {%8,%9}, {%0,%1,%2,%3};"
        : "+f"(c[0]), "+f"(c[1]), "+f"(c[2]), "+f"(c[3])
        : "r"(a[0]), "r"(a[1]), "r"(a[2]), "r"(a[3]), "r"(b[0]), "r"(b[1]));
}

__global__ void __launch_bounds__(128, 2)
fa_kernel(const float* __restrict__ q, const float* __restrict__ k,
          const float* __restrict__ v, const float* __restrict__ bias,
          float* __restrict__ out)
{
    __shared__ __align__(16) uint32_t sK[BN * KP];       // K tile, f16x2 d-pairs
    __shared__ __align__(16) uint32_t sV[(BN/2) * VP];   // V tile, f16x2 seq row-pairs

    const int tid  = threadIdx.x;
    const int lane = tid & 31;
    const int wid  = tid >> 5;
    const int g    = lane >> 2;
    const int c    = lane & 3;

    // grid: batch fastest-varying (bias L2 reuse); qt reversed (longest first)
    const int idx = blockIdx.x;
    const int b   = idx & 3;
    const int h   = (idx >> 2) & 15;
    const int qt  = (Ss / BM - 1) - (idx >> 6);
    const int qrow = qt * BM;

    // each warp owns 32 rows: two m16 row blocks
    const int rw  = qrow + wid * 32 + g;
    const int r00 = rw,      r01 = rw + 8;     // row block 0
    const int r10 = rw + 16, r11 = rw + 24;    // row block 1

    // ---- Q fragments (f16x2), loaded once: qa[rb][ks][4] ----
    uint32_t qa[2][4][4];
    {
        const float* q00 = q + ((size_t)(b * Ss + r00) * Hh + h) * Dd;
        const float* q01 = q + ((size_t)(b * Ss + r01) * Hh + h) * Dd;
        const float* q10 = q + ((size_t)(b * Ss + r10) * Hh + h) * Dd;
        const float* q11 = q + ((size_t)(b * Ss + r11) * Hh + h) * Dd;
#pragma unroll
        for (int ks = 0; ks < 4; ks++) {
            const int d0 = ks * 16 + 2 * c;
            float2 x, y;
            x = *(const float2*)(q00 + d0);     qa[0][ks][0] = packf16x2(x.x, x.y);
            x = *(const float2*)(q01 + d0);     qa[0][ks][1] = packf16x2(x.x, x.y);
            x = *(const float2*)(q00 + d0 + 8); qa[0][ks][2] = packf16x2(x.x, x.y);
            x = *(const float2*)(q01 + d0 + 8); qa[0][ks][3] = packf16x2(x.x, x.y);
            y = *(const float2*)(q10 + d0);     qa[1][ks][0] = packf16x2(y.x, y.y);
            y = *(const float2*)(q11 + d0);     qa[1][ks][1] = packf16x2(y.x, y.y);
            y = *(const float2*)(q10 + d0 + 8); qa[1][ks][2] = packf16x2(y.x, y.y);
            y = *(const float2*)(q11 + d0 + 8); qa[1][ks][3] = packf16x2(y.x, y.y);
        }
    }

    float oacc[2][8][4];
#pragma unroll
    for (int rb = 0; rb < 2; rb++)
#pragma unroll
        for (int i = 0; i < 8; i++) {
            oacc[rb][i][0] = 0.f; oacc[rb][i][1] = 0.f;
            oacc[rb][i][2] = 0.f; oacc[rb][i][3] = 0.f;
        }
    float lacc0[4] = {0.f, 0.f, 0.f, 0.f};
    float lacc1[4] = {0.f, 0.f, 0.f, 0.f};
    float m00 = NEGINF, m01 = NEGINF, m10 = NEGINF, m11 = NEGINF;

    // ones-column B fragment for row-sum mma (column n=0, lanes g==0)
    const uint32_t onesw = (g == 0) ? 0x3C003C00u : 0u;
    const uint32_t onesb[2] = {onesw, onesw};

    const float* b00 = bias + ((size_t)h * Ss + r00) * Ss;
    const float* b01 = bias + ((size_t)h * Ss + r01) * Ss;
    const float* b10 = bias + ((size_t)h * Ss + r10) * Ss;
    const float* b11 = bias + ((size_t)h * Ss + r11) * Ss;

    const int nj = 2 * qt + 2;
    for (int j = 0; j < nj; j++) {
        __syncthreads();
        const size_t base = ((size_t)(b * Ss + j * BN) * Hh + h) * Dd;

        // ---- K tile: fp32 -> f16x2 d-pairs -> smem ----
#pragma unroll
        for (int it = 0; it < 8; it++) {
            const int t  = it * 128 + tid;
            const int n  = t >> 4;
            const int d4 = (t & 15) << 2;
            const float4 kv = *(const float4*)(k + base + (size_t)n * (Hh * Dd) + d4);
            uint2 kt;
            kt.x = packf16x2(kv.x, kv.y);
            kt.y = packf16x2(kv.z, kv.w);
            *(uint2*)(&sK[n * KP + (d4 >> 1)]) = kt;
        }
        // ---- V tile: fp32 seq row-pairs -> f16x2 -> smem ----
#pragma unroll
        for (int it = 0; it < 4; it++) {
            const int t  = it * 128 + tid;
            const int rp = t >> 4;
            const int d4 = (t & 15) << 2;
            const float* vb = v + base + (size_t)(2 * rp) * (Hh * Dd) + d4;
            const float4 v0 = *(const float4*)(vb);
            const float4 v1 = *(const float4*)(vb + Hh * Dd);
            uint4 hi;
            hi.x = packf16x2(v0.x, v1.x);
            hi.y = packf16x2(v0.y, v1.y);
            hi.z = packf16x2(v0.z, v1.z);
            hi.w = packf16x2(v0.w, v1.w);
            *(uint4*)(&sV[rp * VP + d4]) = hi;
        }
        __syncthreads();

        // ---- S = Q K^T : each B fragment feeds both row blocks ----
        float sacc[2][8][4];
#pragma unroll
        for (int nf = 0; nf < 8; nf++) {
            sacc[0][nf][0] = 0.f; sacc[0][nf][1] = 0.f; sacc[0][nf][2] = 0.f; sacc[0][nf][3] = 0.f;
            sacc[1][nf][0] = 0.f; sacc[1][nf][1] = 0.f; sacc[1][nf][2] = 0.f; sacc[1][nf][3] = 0.f;
#pragma unroll
            for (int ks = 0; ks < 4; ks++) {
                const uint32_t* kp = &sK[(nf * 8 + g) * KP + ks * 8 + c];
                uint32_t bfr[2];
                bfr[0] = kp[0];
                bfr[1] = kp[4];
                mma_f16(sacc[0][nf], qa[0][ks], bfr);
                mma_f16(sacc[1][nf], qa[1][ks], bfr);
            }
        }

        // ---- scale + bias + causal mask ----
        const int kcb = j * BN;
        const bool diag = (j >= 2 * qt);
#pragma unroll
        for (int nf = 0; nf < 8; nf++) {
            const int kc = kcb + nf * 8 + 2 * c;
            const float2 bb00 = __ldg((const float2*)(b00 + kc));
            const float2 bb01 = __ldg((const float2*)(b01 + kc));
            const float2 bb10 = __ldg((const float2*)(b10 + kc));
            const float2 bb11 = __ldg((const float2*)(b11 + kc));
            sacc[0][nf][0] = sacc[0][nf][0] * SCALE + bb00.x;
            sacc[0][nf][1] = sacc[0][nf][1] * SCALE + bb00.y;
            sacc[0][nf][2] = sacc[0][nf][2] * SCALE + bb01.x;
            sacc[0][nf][3] = sacc[0][nf][3] * SCALE + bb01.y;
            sacc[1][nf][0] = sacc[1][nf][0] * SCALE + bb10.x;
            sacc[1][nf][1] = sacc[1][nf][1] * SCALE + bb10.y;
            sacc[1][nf][2] = sacc[1][nf][2] * SCALE + bb11.x;
            sacc[1][nf][3] = sacc[1][nf][3] * SCALE + bb11.y;
            if (diag) {
                if (kc     > r00) sacc[0][nf][0] = NEGINF;
                if (kc + 1 > r00) sacc[0][nf][1] = NEGINF;
                if (kc     > r01) sacc[0][nf][2] = NEGINF;
                if (kc + 1 > r01) sacc[0][nf][3] = NEGINF;
                if (kc     > r10) sacc[1][nf][0] = NEGINF;
                if (kc + 1 > r10) sacc[1][nf][1] = NEGINF;
                if (kc     > r11) sacc[1][nf][2] = NEGINF;
                if (kc + 1 > r11) sacc[1][nf][3] = NEGINF;
            }
        }

        // ---- online softmax: maxes only ----
        float rm00 = NEGINF, rm01 = NEGINF, rm10 = NEGINF, rm11 = NEGINF;
#pragma unroll
        for (int nf = 0; nf < 8; nf++) {
            rm00 = fmaxf(rm00, fmaxf(sacc[0][nf][0], sacc[0][nf][1]));
            rm01 = fmaxf(rm01, fmaxf(sacc[0][nf][2], sacc[0][nf][3]));
            rm10 = fmaxf(rm10, fmaxf(sacc[1][nf][0], sacc[1][nf][1]));
            rm11 = fmaxf(rm11, fmaxf(sacc[1][nf][2], sacc[1][nf][3]));
        }
        rm00 = fmaxf(rm00, __shfl_xor_sync(0xffffffffu, rm00, 1));
        rm00 = fmaxf(rm00, __shfl_xor_sync(0xffffffffu, rm00, 2));
        rm01 = fmaxf(rm01, __shfl_xor_sync(0xffffffffu, rm01, 1));
        rm01 = fmaxf(rm01, __shfl_xor_sync(0xffffffffu, rm01, 2));
        rm10 = fmaxf(rm10, __shfl_xor_sync(0xffffffffu, rm10, 1));
        rm10 = fmaxf(rm10, __shfl_xor_sync(0xffffffffu, rm10, 2));
        rm11 = fmaxf(rm11, __shfl_xor_sync(0xffffffffu, rm11, 1));
        rm11 = fmaxf(rm11, __shfl_xor_sync(0xffffffffu, rm11, 2));

        const float nm00 = fmaxf(m00, rm00), nm01 = fmaxf(m01, rm01);
        const float nm10 = fmaxf(m10, rm10), nm11 = fmaxf(m11, rm11);
        const float a00 = __expf(m00 - nm00), a01 = __expf(m01 - nm01);
        const float a10 = __expf(m10 - nm10), a11 = __expf(m11 - nm11);
        m00 = nm00; m01 = nm01; m10 = nm10; m11 = nm11;
        const float mL00 = nm00 * LOG2E, mL01 = nm01 * LOG2E;
        const float mL10 = nm10 * LOG2E, mL11 = nm11 * LOG2E;

        lacc0[0] *= a00; lacc0[1] *= a00; lacc0[2] *= a01; lacc0[3] *= a01;
        lacc1[0] *= a10; lacc1[1] *= a10; lacc1[2] *= a11; lacc1[3] *= a11;
#pragma unroll
        for (int df = 0; df < 8; df++) {
            oacc[0][df][0] *= a00; oacc[0][df][1] *= a00;
            oacc[0][df][2] *= a01; oacc[0][df][3] *= a01;
            oacc[1][df][0] *= a10; oacc[1][df][1] *= a10;
            oacc[1][df][2] *= a11; oacc[1][df][3] *= a11;
        }

        // ---- P = ex2(...) fp16; O += P V; l += P·1 : V frags feed both row blocks ----
#pragma unroll
        for (int t = 0; t < 4; t++) {
            uint32_t af0[4], af1[4];
            af0[0] = ex2h2(packf16x2(fmaf(sacc[0][2*t][0],   LOG2E, -mL00),
                                     fmaf(sacc[0][2*t][1],   LOG2E, -mL00)));
            af0[1] = ex2h2(packf16x2(fmaf(sacc[0][2*t][2],   LOG2E, -mL01),
                                     fmaf(sacc[0][2*t][3],   LOG2E, -mL01)));
            af0[2] = ex2h2(packf16x2(fmaf(sacc[0][2*t+1][0], LOG2E, -mL00),
                                     fmaf(sacc[0][2*t+1][1], LOG2E, -mL00)));
            af0[3] = ex2h2(packf16x2(fmaf(sacc[0][2*t+1][2], LOG2E, -mL01),
                                     fmaf(sacc[0][2*t+1][3], LOG2E, -mL01)));
            af1[0] = ex2h2(packf16x2(fmaf(sacc[1][2*t][0],   LOG2E, -mL10),
                                     fmaf(sacc[1][2*t][1],   LOG2E, -mL10)));
            af1[1] = ex2h2(packf16x2(fmaf(sacc[1][2*t][2],   LOG2E, -mL11),
                                     fmaf(sacc[1][2*t][3],   LOG2E, -mL11)));
            af1[2] = ex2h2(packf16x2(fmaf(sacc[1][2*t+1][0], LOG2E, -mL10),
                                     fmaf(sacc[1][2*t+1][1], LOG2E, -mL10)));
            af1[3] = ex2h2(packf16x2(fmaf(sacc[1][2*t+1][2], LOG2E, -mL11),
                                     fmaf(sacc[1][2*t+1][3], LOG2E, -mL11)));

            mma_f16(lacc0, af0, onesb);
            mma_f16(lacc1, af1, onesb);

            const int rpb = t * 8 + c;
#pragma unroll
            for (int df = 0; df < 8; df++) {
                const uint32_t* vh = &sV[rpb * VP + df * 8 + g];
                uint32_t bfr[2];
                bfr[0] = vh[0];
                bfr[1] = vh[4 * VP];
                mma_f16(oacc[0][df], af0, bfr);
                mma_f16(oacc[1][df], af1, bfr);
            }
        }
    }

    // ---- epilogue: broadcast row sums (lanes c==0), normalize, store ----
    const float l00 = __shfl_sync(0xffffffffu, lacc0[0], lane & ~3);
    const float l01 = __shfl_sync(0xffffffffu, lacc0[2], lane & ~3);
    const float l10 = __shfl_sync(0xffffffffu, lacc1[0], lane & ~3);
    const float l11 = __shfl_sync(0xffffffffu, lacc1[2], lane & ~3);
    const float i00 = 1.0f / l00, i01 = 1.0f / l01;
    const float i10 = 1.0f / l10, i11 = 1.0f / l11;

    float* o00 = out + ((size_t)(b * Ss + r00) * Hh + h) * Dd;
    float* o01 = out + ((size_t)(b * Ss + r01) * Hh + h) * Dd;
    float* o10 = out + ((size_t)(b * Ss + r10) * Hh + h) * Dd;
    float* o11 = out + ((size_t)(b * Ss + r11) * Hh + h) * Dd;
#pragma unroll
    for (int df = 0; df < 8; df++) {
        const int dc = df * 8 + 2 * c;
        float2 w;
        w.x = oacc[0][df][0] * i00; w.y = oacc[0][df][1] * i00; *(float2*)(o00 + dc) = w;
        w.x = oacc[0][df][2] * i01; w.y = oacc[0][df][3] * i01; *(float2*)(o01 + dc) = w;
        w.x = oacc[1][df][0] * i10; w.y = oacc[1][df][1] * i10; *(float2*)(o10 + dc) = w;
        w.x = oacc[1][df][2] * i11; w.y = oacc[1][df][3] * i11; *(float2*)(o11 + dc) = w;
    }
}

} // namespace

extern "C" void kernel_launch(void* const* d_in, const int* in_sizes, int n_in,
                              void* d_out, int out_size)
{
    const float* q    = (const float*)d_in[0];
    const float* k    = (const float*)d_in[1];
    const float* v    = (const float*)d_in[2];
    const float* bias = (const float*)d_in[3];
    float* out        = (float*)d_out;

    const dim3 grid(Bb * Hh * (Ss / BM));  // 1024 CTAs, batch fastest-varying
    fa_kernel<<<grid, 128>>>(q, k, v, bias, out);
}